// round 7
// baseline (speedup 1.0000x reference)
#include <cuda_runtime.h>
#include <math.h>

#define NB 8
#define NS 2048
#define ND 256
#define NE 256
static constexpr float kScale = 0.125f;  // 1/sqrt(64), per reference source

typedef unsigned long long u64;

// ---- packed f32x2 helpers (SASS FFMA2/FMUL2 — ptxas never emits these) ----
__device__ __forceinline__ u64 pack2(float x, float y) {
    u64 r;
    asm("mov.b64 %0, {%1, %2};" : "=l"(r) : "r"(__float_as_uint(x)), "r"(__float_as_uint(y)));
    return r;
}
__device__ __forceinline__ void unpack2(u64 v, float& x, float& y) {
    unsigned lo, hi;
    asm("mov.b64 {%0, %1}, %2;" : "=r"(lo), "=r"(hi) : "l"(v));
    x = __uint_as_float(lo);
    y = __uint_as_float(hi);
}
__device__ __forceinline__ void ffma2(u64& d, u64 a, u64 b) {
    asm("fma.rn.f32x2 %0, %1, %2, %0;" : "+l"(d) : "l"(a), "l"(b));
}
__device__ __forceinline__ void fmul2(u64& d, u64 a) {
    asm("mul.rn.f32x2 %0, %0, %1;" : "+l"(d) : "l"(a));
}

// ---- cp.async primitives with explicit group control ----
__device__ __forceinline__ void cp16(void* smem_dst, const void* gmem_src) {
    unsigned dst = (unsigned)__cvta_generic_to_shared(smem_dst);
    asm volatile("cp.async.cg.shared.global [%0], [%1], 16;" :: "r"(dst), "l"(gmem_src));
}
__device__ __forceinline__ void cp_commit() {
    asm volatile("cp.async.commit_group;" ::: "memory");
}
__device__ __forceinline__ void cp_wait0() {
    asm volatile("cp.async.wait_group 0;" ::: "memory");
}
__device__ __forceinline__ void cp_wait1() {
    asm volatile("cp.async.wait_group 1;" ::: "memory");
}

// Scratch for Q, K, V projections (allocation-free: __device__ globals)
__device__ float g_Q[NB * NS * NE];
__device__ float g_K[NB * NS * NE];
__device__ float g_V[NB * NS * NE];

// ---------------------------------------------------------------------------
// QKV projection: computes ALL THREE C_p = X @ W_p per block so X is read
// once (memory-bound kernel: traffic 256MB vs 384MB before).
// 64x64 tile, 4x4 micro tile per thread per projection. FFMA2.
// ---------------------------------------------------------------------------
__global__ __launch_bounds__(256) void qkv_kernel(const float* __restrict__ x,
                                                  const float* __restrict__ w) {
    __shared__ __align__(16) float As[64][20];
    __shared__ __align__(16) float Bs[3][16][68];

    const int row0 = blockIdx.x * 64;
    const int col0 = blockIdx.y * 64;
    const int tid = threadIdx.x;
    const int tx = tid & 15;
    const int ty = tid >> 4;

    ulonglong2 acc[3][4];
#pragma unroll
    for (int p = 0; p < 3; p++)
#pragma unroll
        for (int i = 0; i < 4; i++) { acc[p][i].x = 0ull; acc[p][i].y = 0ull; }

    for (int k0 = 0; k0 < ND; k0 += 16) {
        {
            int r = tid >> 2;
            int c = (tid & 3) << 2;
            cp16(&As[r][c], &x[(size_t)(row0 + r) * ND + k0 + c]);
        }
        {
            int r = tid >> 4;
            int c = (tid & 15) << 2;
#pragma unroll
            for (int p = 0; p < 3; p++)
                cp16(&Bs[p][r][c], &w[(size_t)p * ND * NE + (size_t)(k0 + r) * NE + col0 + c]);
        }
        cp_commit();
        cp_wait0();
        __syncthreads();
#pragma unroll
        for (int kk = 0; kk < 16; kk++) {
            ulonglong2 bv[3];
#pragma unroll
            for (int p = 0; p < 3; p++) bv[p] = *(const ulonglong2*)&Bs[p][kk][tx << 2];
#pragma unroll
            for (int i = 0; i < 4; i++) {
                float a = As[(ty << 2) + i][kk];
                u64 ap = pack2(a, a);
#pragma unroll
                for (int p = 0; p < 3; p++) {
                    ffma2(acc[p][i].x, ap, bv[p].x);
                    ffma2(acc[p][i].y, ap, bv[p].y);
                }
            }
        }
        __syncthreads();
    }
#pragma unroll
    for (int i = 0; i < 4; i++) {
        size_t off = (size_t)(row0 + (ty << 2) + i) * NE + col0 + (tx << 2);
        *(ulonglong2*)&g_Q[off] = acc[0][i];
        *(ulonglong2*)&g_K[off] = acc[1][i];
        *(ulonglong2*)&g_V[off] = acc[2][i];
    }
}

// ---------------------------------------------------------------------------
// Flash-attention, 256 threads (8 warps). Warp wy owns query rows wy+8i (i<8);
// lane tx owns key cols tx+32j (j<2) and output cols tx*4+128*cc (cc<2).
// 8 rows per warp halves the K/V smem-crossbar redundancy vs 16 warps
// (crossbar was the measured bottleneck: L1 73.7% vs fma 44%).
// K/V tiles software-pipelined through single buffers via cp.async groups.
// ---------------------------------------------------------------------------
__global__ __launch_bounds__(256, 1) void attn_kernel(const int* __restrict__ mask,
                                                      float* __restrict__ out) {
    extern __shared__ float sm[];
    float* Qs = sm;               // [64][260]
    float* Ks = Qs + 64 * 260;    // [64][260]
    float* Vs = Ks + 64 * 260;    // [64][260]
    float* Ps = Vs + 64 * 260;    // [64][68]
    float* rs = Ps + 64 * 68;     // [64]

    const int b  = blockIdx.y;
    const int q0 = blockIdx.x * 64;
    const float* __restrict__ Qg = g_Q + (size_t)b * NS * NE;
    const float* __restrict__ Kg = g_K + (size_t)b * NS * NE;
    const float* __restrict__ Vg = g_V + (size_t)b * NS * NE;

    const int tid = threadIdx.x;
    const int tx = tid & 31;   // lane
    const int wy = tid >> 5;   // warp id (0..7): query row group

    // --- preload: Q (group), K0 (group), V0 (group); rs via plain STS ---
    for (int i = tid; i < 64 * 64; i += 256) {
        int r = i >> 6, c = (i & 63) << 2;
        cp16(&Qs[r * 260 + c], &Qg[(size_t)(q0 + r) * NE + c]);
    }
    cp_commit();
    for (int i = tid; i < 64 * 64; i += 256) {
        int r = i >> 6, c = (i & 63) << 2;
        cp16(&Ks[r * 260 + c], &Kg[(size_t)r * NE + c]);
    }
    cp_commit();
    for (int i = tid; i < 64 * 64; i += 256) {
        int r = i >> 6, c = (i & 63) << 2;
        cp16(&Vs[r * 260 + c], &Vg[(size_t)r * NE + c]);
    }
    cp_commit();
    if (tid < 64) rs[tid] = kScale * (float)mask[b * NS + q0 + tid];
    __syncthreads();  // rs visible (cp groups still in flight)

    int qr[8];
    float rscale[8];
#pragma unroll
    for (int i = 0; i < 8; i++) { qr[i] = wy + 8 * i; rscale[i] = rs[qr[i]]; }

    ulonglong2 O2[8][2];
#pragma unroll
    for (int i = 0; i < 8; i++)
#pragma unroll
        for (int cc = 0; cc < 2; cc++) { O2[i][cc].x = 0ull; O2[i][cc].y = 0ull; }

    float m_run[8], l_run[8];
#pragma unroll
    for (int i = 0; i < 8; i++) { m_run[i] = -INFINITY; l_run[i] = 0.f; }

    for (int kt = 0; kt < NS / 64; kt++) {
        cp_wait1();        // K(kt) resident (thread-local), V(kt) may be in flight
        __syncthreads();   // all threads' K parts visible

        // ---- QK: 8 rows x 2 key cols per lane, register double-buffered ----
        u64 s2[8][2];
#pragma unroll
        for (int i = 0; i < 8; i++)
#pragma unroll
            for (int j = 0; j < 2; j++) s2[i][j] = 0ull;

        ulonglong2 qn[8], kn[2];
#pragma unroll
        for (int i = 0; i < 8; i++) qn[i] = *(const ulonglong2*)&Qs[qr[i] * 260];
        kn[0] = *(const ulonglong2*)&Ks[tx * 260];
        kn[1] = *(const ulonglong2*)&Ks[(tx + 32) * 260];

#pragma unroll 4
        for (int e = 0; e < NE; e += 4) {
            ulonglong2 qc[8], kc[2];
#pragma unroll
            for (int i = 0; i < 8; i++) qc[i] = qn[i];
            kc[0] = kn[0];
            kc[1] = kn[1];
            // prefetch next step (e=252 reads the 4-float row pad: in-bounds)
#pragma unroll
            for (int i = 0; i < 8; i++) qn[i] = *(const ulonglong2*)&Qs[qr[i] * 260 + e + 4];
            kn[0] = *(const ulonglong2*)&Ks[tx * 260 + e + 4];
            kn[1] = *(const ulonglong2*)&Ks[(tx + 32) * 260 + e + 4];
#pragma unroll
            for (int i = 0; i < 8; i++)
#pragma unroll
                for (int j = 0; j < 2; j++) {
                    ffma2(s2[i][j], qc[i].x, kc[j].x);
                    ffma2(s2[i][j], qc[i].y, kc[j].y);
                }
        }

        // ---- softmax (full-warp reductions), 8 rows per lane ----
        float p[8][2];
#pragma unroll
        for (int i = 0; i < 8; i++) {
            float s[2];
#pragma unroll
            for (int j = 0; j < 2; j++) {
                float lo, hi;
                unpack2(s2[i][j], lo, hi);
                s[j] = (lo + hi) * rscale[i];
            }
            float mt = fmaxf(s[0], s[1]);
            mt = fmaxf(mt, __shfl_xor_sync(0xffffffffu, mt, 16));
            mt = fmaxf(mt, __shfl_xor_sync(0xffffffffu, mt, 8));
            mt = fmaxf(mt, __shfl_xor_sync(0xffffffffu, mt, 4));
            mt = fmaxf(mt, __shfl_xor_sync(0xffffffffu, mt, 2));
            mt = fmaxf(mt, __shfl_xor_sync(0xffffffffu, mt, 1));
            float mn = fmaxf(m_run[i], mt);

            float sum = 0.f;
#pragma unroll
            for (int j = 0; j < 2; j++) {
                p[i][j] = __expf(s[j] - mn);
                sum += p[i][j];
            }
            sum += __shfl_xor_sync(0xffffffffu, sum, 16);
            sum += __shfl_xor_sync(0xffffffffu, sum, 8);
            sum += __shfl_xor_sync(0xffffffffu, sum, 4);
            sum += __shfl_xor_sync(0xffffffffu, sum, 2);
            sum += __shfl_xor_sync(0xffffffffu, sum, 1);

            float alpha = __expf(m_run[i] - mn);  // 0 on first tile
            l_run[i] = l_run[i] * alpha + sum;
            m_run[i] = mn;
            u64 a2 = pack2(alpha, alpha);
#pragma unroll
            for (int cc = 0; cc < 2; cc++) {
                fmul2(O2[i][cc].x, a2);
                fmul2(O2[i][cc].y, a2);
            }
        }

        // P rows wy+8i produced & consumed by warp wy only
#pragma unroll
        for (int i = 0; i < 8; i++)
#pragma unroll
            for (int j = 0; j < 2; j++) Ps[qr[i] * 68 + tx + 32 * j] = p[i][j];
        __syncwarp();

        cp_wait0();        // V(kt) resident (thread-local)
        __syncthreads();   // all V parts visible AND all warps done reading Ks

        // prefetch K(kt+1) into Ks — overlaps the PV phase
        if (kt + 1 < NS / 64) {
            const float* Kn = Kg + (size_t)(kt + 1) * 64 * NE;
            for (int i = tid; i < 64 * 64; i += 256) {
                int r = i >> 6, c = (i & 63) << 2;
                cp16(&Ks[r * 260 + c], &Kn[(size_t)r * NE + c]);
            }
            cp_commit();
        }

        // ---- PV: 8 rows x 8 out cols per lane, register double-buffered ----
        ulonglong2 vn[2];
        vn[0] = *(const ulonglong2*)&Vs[(tx << 2)];
        vn[1] = *(const ulonglong2*)&Vs[(tx << 2) + 128];
        float pn[8];
#pragma unroll
        for (int i = 0; i < 8; i++) pn[i] = Ps[qr[i] * 68];

#pragma unroll 4
        for (int j = 0; j < 64; j++) {
            ulonglong2 vc[2];
            vc[0] = vn[0];
            vc[1] = vn[1];
            u64 pp[8];
#pragma unroll
            for (int i = 0; i < 8; i++) pp[i] = pack2(pn[i], pn[i]);
            // prefetch next step (j=63 reads into Ps region: in smem bounds)
            vn[0] = *(const ulonglong2*)&Vs[(j + 1) * 260 + (tx << 2)];
            vn[1] = *(const ulonglong2*)&Vs[(j + 1) * 260 + (tx << 2) + 128];
#pragma unroll
            for (int i = 0; i < 8; i++) pn[i] = Ps[qr[i] * 68 + j + 1];
#pragma unroll
            for (int i = 0; i < 8; i++)
#pragma unroll
                for (int cc = 0; cc < 2; cc++) {
                    ffma2(O2[i][cc].x, pp[i], vc[cc].x);
                    ffma2(O2[i][cc].y, pp[i], vc[cc].y);
                }
        }
        __syncthreads();   // all warps done reading Vs

        // prefetch V(kt+1) into Vs — overlaps next tile's QK phase
        if (kt + 1 < NS / 64) {
            const float* Vn = Vg + (size_t)(kt + 1) * 64 * NE;
            for (int i = tid; i < 64 * 64; i += 256) {
                int r = i >> 6, c = (i & 63) << 2;
                cp16(&Vs[r * 260 + c], &Vn[(size_t)r * NE + c]);
            }
            cp_commit();
        }
    }

    // Epilogue: normalize (packed) and store 16B per (i,cc)
#pragma unroll
    for (int i = 0; i < 8; i++) {
        float inv = 1.0f / l_run[i];
        u64 inv2 = pack2(inv, inv);
#pragma unroll
        for (int cc = 0; cc < 2; cc++) {
            fmul2(O2[i][cc].x, inv2);
            fmul2(O2[i][cc].y, inv2);
            *(ulonglong2*)&out[(size_t)(b * NS + q0 + qr[i]) * NE + (tx << 2) + 128 * cc] =
                O2[i][cc];
        }
    }
}

// ---------------------------------------------------------------------------
extern "C" void kernel_launch(void* const* d_in, const int* in_sizes, int n_in,
                              void* d_out, int out_size) {
    (void)in_sizes; (void)n_in; (void)out_size;
    const float* x    = (const float*)d_in[0];  // [8, 2048, 256] f32
    const float* w    = (const float*)d_in[1];  // [3, 256, 256]  f32
    const int*   mask = (const int*)d_in[2];    // [8, 2048]      i32
    float* out = (float*)d_out;                 // [8, 2048, 256] f32

    dim3 g1((NB * NS) / 64, NE / 64);
    qkv_kernel<<<g1, 256>>>(x, w);

    const size_t smem = (size_t)(3 * 64 * 260 + 64 * 68 + 64) * sizeof(float);  // 217,344 B
    cudaFuncSetAttribute(attn_kernel, cudaFuncAttributeMaxDynamicSharedMemorySize,
                         (int)smem);
    dim3 g2(NS / 64, NB);
    attn_kernel<<<g2, 256, smem>>>(mask, out);
}

// round 10
// speedup vs baseline: 1.7017x; 1.7017x over previous
#include <cuda_runtime.h>
#include <cuda_bf16.h>
#include <math.h>
#include <stdint.h>

#define NB 8
#define NS 2048
#define ND 256
#define NE 256
static constexpr float kScale = 0.125f;  // 1/sqrt(64), per reference source

typedef unsigned long long u64;
typedef uint32_t u32;
typedef unsigned short u16;

// ---------------- packed f32x2 (prep GEMM) ----------------
__device__ __forceinline__ u64 pack2(float x, float y) {
    u64 r;
    asm("mov.b64 %0, {%1, %2};" : "=l"(r) : "r"(__float_as_uint(x)), "r"(__float_as_uint(y)));
    return r;
}
__device__ __forceinline__ void unpack2(u64 v, float& x, float& y) {
    unsigned lo, hi;
    asm("mov.b64 {%0, %1}, %2;" : "=r"(lo), "=r"(hi) : "l"(v));
    x = __uint_as_float(lo);
    y = __uint_as_float(hi);
}
__device__ __forceinline__ void ffma2(u64& d, u64 a, u64 b) {
    asm("fma.rn.f32x2 %0, %1, %2, %0;" : "+l"(d) : "l"(a), "l"(b));
}

// ---------------- cp.async ----------------
__device__ __forceinline__ void cp16(u32 smem_dst, const void* gmem_src) {
    asm volatile("cp.async.cg.shared.global [%0], [%1], 16;" :: "r"(smem_dst), "l"(gmem_src));
}
__device__ __forceinline__ void cp_commit() {
    asm volatile("cp.async.commit_group;" ::: "memory");
}
__device__ __forceinline__ void cp_wait0() { asm volatile("cp.async.wait_group 0;" ::: "memory"); }
__device__ __forceinline__ void cp_wait1() { asm volatile("cp.async.wait_group 1;" ::: "memory"); }

// ---------------- mma.sync / ldmatrix (family-wide, works on sm_103) ----------
__device__ __forceinline__ void ldsm4(u32* d, u32 addr) {
    asm volatile("ldmatrix.sync.aligned.m8n8.x4.shared.b16 {%0,%1,%2,%3}, [%4];"
        : "=r"(d[0]), "=r"(d[1]), "=r"(d[2]), "=r"(d[3]) : "r"(addr));
}
__device__ __forceinline__ void mma_bf16(float* c, const u32* a, u32 b0, u32 b1) {
    asm volatile("mma.sync.aligned.m16n8k16.row.col.f32.bf16.bf16.f32 "
        "{%0,%1,%2,%3}, {%4,%5,%6,%7}, {%8,%9}, {%0,%1,%2,%3};"
        : "+f"(c[0]), "+f"(c[1]), "+f"(c[2]), "+f"(c[3])
        : "r"(a[0]), "r"(a[1]), "r"(a[2]), "r"(a[3]), "r"(b0), "r"(b1));
}

// ---------------- global bf16 scratch ----------------
// Q, K row-major [b*NS + s][e];  Vt e-major [b][e][key]
__device__ __align__(16) __nv_bfloat16 gQh[NB * NS * NE];
__device__ __align__(16) __nv_bfloat16 gQl[NB * NS * NE];
__device__ __align__(16) __nv_bfloat16 gKh[NB * NS * NE];
__device__ __align__(16) __nv_bfloat16 gKl[NB * NS * NE];
__device__ __align__(16) __nv_bfloat16 gVth[NB * NE * NS];
__device__ __align__(16) __nv_bfloat16 gVtl[NB * NE * NS];

// ---------------------------------------------------------------------------
// Prep: fp32 QKV GEMM (FFMA2) + bf16 hi/lo split stores.
// ---------------------------------------------------------------------------
__global__ __launch_bounds__(256) void qkv_prep(const float* __restrict__ x,
                                                const float* __restrict__ w) {
    __shared__ __align__(16) float As[64][20];
    __shared__ __align__(16) float Bs[3][16][68];

    const int row0 = blockIdx.x * 64;
    const int col0 = blockIdx.y * 64;
    const int tid = threadIdx.x;
    const int tx = tid & 15;
    const int ty = tid >> 4;

    ulonglong2 acc[3][4];
#pragma unroll
    for (int p = 0; p < 3; p++)
#pragma unroll
        for (int i = 0; i < 4; i++) { acc[p][i].x = 0ull; acc[p][i].y = 0ull; }

    for (int k0 = 0; k0 < ND; k0 += 16) {
        {
            int r = tid >> 2, c = (tid & 3) << 2;
            cp16((u32)__cvta_generic_to_shared(&As[r][c]), &x[(size_t)(row0 + r) * ND + k0 + c]);
        }
        {
            int r = tid >> 4, c = (tid & 15) << 2;
#pragma unroll
            for (int p = 0; p < 3; p++)
                cp16((u32)__cvta_generic_to_shared(&Bs[p][r][c]),
                     &w[(size_t)p * ND * NE + (size_t)(k0 + r) * NE + col0 + c]);
        }
        cp_commit();
        cp_wait0();
        __syncthreads();
#pragma unroll
        for (int kk = 0; kk < 16; kk++) {
            ulonglong2 bv[3];
#pragma unroll
            for (int p = 0; p < 3; p++) bv[p] = *(const ulonglong2*)&Bs[p][kk][tx << 2];
#pragma unroll
            for (int i = 0; i < 4; i++) {
                float a = As[(ty << 2) + i][kk];
                u64 ap = pack2(a, a);
#pragma unroll
                for (int p = 0; p < 3; p++) {
                    ffma2(acc[p][i].x, ap, bv[p].x);
                    ffma2(acc[p][i].y, ap, bv[p].y);
                }
            }
        }
        __syncthreads();
    }

    auto split4 = [](const ulonglong2& a, float* f) {
        unpack2(a.x, f[0], f[1]);
        unpack2(a.y, f[2], f[3]);
    };
    auto pack4 = [](const float* f, uint2& hi, uint2& lo) {
        u16 h[4], l[4];
#pragma unroll
        for (int j = 0; j < 4; j++) {
            __nv_bfloat16 hb = __float2bfloat16_rn(f[j]);
            __nv_bfloat16 lb = __float2bfloat16_rn(f[j] - __bfloat162float(hb));
            h[j] = __bfloat16_as_ushort(hb);
            l[j] = __bfloat16_as_ushort(lb);
        }
        hi.x = (u32)h[0] | ((u32)h[1] << 16); hi.y = (u32)h[2] | ((u32)h[3] << 16);
        lo.x = (u32)l[0] | ((u32)l[1] << 16); lo.y = (u32)l[2] | ((u32)l[3] << 16);
    };

    float vf[4][4];
#pragma unroll
    for (int i = 0; i < 4; i++) {
        size_t off = (size_t)(row0 + (ty << 2) + i) * NE + col0 + (tx << 2);
        float f[4];
        uint2 hi, lo;
        split4(acc[0][i], f); pack4(f, hi, lo);
        *(uint2*)&gQh[off] = hi; *(uint2*)&gQl[off] = lo;
        split4(acc[1][i], f); pack4(f, hi, lo);
        *(uint2*)&gKh[off] = hi; *(uint2*)&gKl[off] = lo;
        split4(acc[2][i], vf[i]);
    }
    // V transposed store: gVt[b][e][key]
    const int b = row0 >> 11;
    const int key0 = (row0 & (NS - 1)) + (ty << 2);
#pragma unroll
    for (int j = 0; j < 4; j++) {
        int e = col0 + (tx << 2) + j;
        float f[4] = {vf[0][j], vf[1][j], vf[2][j], vf[3][j]};
        uint2 hi, lo;
        pack4(f, hi, lo);
        size_t off = (size_t)b * NE * NS + (size_t)e * NS + key0;
        *(uint2*)&gVth[off] = hi; *(uint2*)&gVtl[off] = lo;
    }
}

// ---------------------------------------------------------------------------
// Attention: 64 q per block, 512 threads (16 warps: 4 q-groups x 4 key/e-grps).
// Two passes; mma.sync.m16n8k16 bf16, 4-way split QK, 3-way split PV.
// SMEM images use 128B atoms + XOR swizzle -> conflict-free ldmatrix.
// ---------------------------------------------------------------------------
#define SM_RS   0                      // 64 floats: row scale
#define SM_RED  256                    // 4*64 floats: max/l reduction
#define SM_QH   2048                   // 64x256 bf16 images, 32KB each
#define SM_QL   (SM_QH + 32768)
#define SM_KH   (SM_QL + 32768)
#define SM_KL   (SM_KH + 32768)
#define SM_VH   (SM_KL + 32768)        // Vt: 256 e-rows x 64 keys
#define SM_VL   (SM_VH + 32768)
#define SM_PH   (SM_VL + 32768)        // P: 64 q-rows x 64 keys, 8KB each
#define SM_PL   (SM_PH + 8192)
#define SM_TOT  (SM_PL + 8192)         // 215040 B

__device__ __forceinline__ u32 swz(u32 o) { return o ^ ((o >> 3) & 0x70); }
// 64-row x 512B image in 1KB atoms (8 rows x 128B), atom = (r>>3) + (cb>>7)*8
__device__ __forceinline__ u32 off64(int r, int cb) {
    return swz((u32)(((r >> 3) + (cb >> 7) * 8) * 1024 + (r & 7) * 128 + (cb & 127)));
}
// 128B-row image (Vt: 256 rows, P: 64 rows)
__device__ __forceinline__ u32 off128(int r, int cb) {
    return swz((u32)(r * 128 + cb));
}

// A-fragment (m16k16): reg g -> rows r0+8*(g&1), col cb+16*(g>>1)
__device__ __forceinline__ void lda(u32* d, u32 base, int r0, int cb, int lane, bool wide) {
    int g = lane >> 3;
    int r = r0 + (lane & 7) + (g & 1) * 8;
    int c = cb + (g >> 1) * 16;
    ldsm4(d, base + (wide ? off64(r, c) : off128(r, c)));
}
// B-fragments for two n-tiles: reg g -> rows n0+8*(g>>1), col cb+16*(g&1)
__device__ __forceinline__ void ldb(u32* d, u32 base, int n0, int cb, int lane, bool wide) {
    int g = lane >> 3;
    int r = n0 + (lane & 7) + (g >> 1) * 8;
    int c = cb + (g & 1) * 16;
    ldsm4(d, base + (wide ? off64(r, c) : off128(r, c)));
}

// global row-major 64x256 bf16 tile -> 64-row image
__device__ __forceinline__ void load64img(u32 base, const __nv_bfloat16* src, int tid) {
    for (int c = tid; c < 2048; c += 512) {
        int r = c >> 5, eb = (c & 31) << 4;
        cp16(base + off64(r, eb), (const char*)src + (size_t)r * 512 + eb);
    }
}
// gVt (row stride NS*2 bytes) 256x64 tile -> 128B-row image
__device__ __forceinline__ void loadvt(u32 base, const __nv_bfloat16* src, int tid) {
    for (int c = tid; c < 2048; c += 512) {
        int e = c >> 3, kb = (c & 7) << 4;
        cp16(base + off128(e, kb), (const char*)src + (size_t)e * (NS * 2) + kb);
    }
}

__device__ __forceinline__ void packsplit(float x, float y, u32& hi, u32& lo) {
    __nv_bfloat16 xh = __float2bfloat16_rn(x), yh = __float2bfloat16_rn(y);
    __nv_bfloat16 xl = __float2bfloat16_rn(x - __bfloat162float(xh));
    __nv_bfloat16 yl = __float2bfloat16_rn(y - __bfloat162float(yh));
    hi = (u32)__bfloat16_as_ushort(xh) | ((u32)__bfloat16_as_ushort(yh) << 16);
    lo = (u32)__bfloat16_as_ushort(xl) | ((u32)__bfloat16_as_ushort(yl) << 16);
}

__global__ __launch_bounds__(512, 1) void attn_mma(const int* __restrict__ mask,
                                                   float* __restrict__ out) {
    extern __shared__ __align__(1024) char smc[];
    const u32 sm = (u32)__cvta_generic_to_shared(smc);
    float* rs = (float*)(smc + SM_RS);
    float* red = (float*)(smc + SM_RED);

    const int b = blockIdx.y, q0 = blockIdx.x * 64;
    const int tid = threadIdx.x, lane = tid & 31, wid = tid >> 5;
    const int wq = wid & 3, wn = wid >> 2;
    const int r0 = wq * 16;
    const int rl = r0 + (lane >> 2), rh = rl + 8;
    const int n0 = wn * 16;          // QK key chunk
    const int e0 = wn * 64;          // PV e chunk

    const __nv_bfloat16* Qh_g = gQh + (size_t)(b * NS + q0) * NE;
    const __nv_bfloat16* Ql_g = gQl + (size_t)(b * NS + q0) * NE;
    const __nv_bfloat16* Kh_g = gKh + (size_t)b * NS * NE;
    const __nv_bfloat16* Kl_g = gKl + (size_t)b * NS * NE;
    const __nv_bfloat16* Vth_g = gVth + (size_t)b * NE * NS;
    const __nv_bfloat16* Vtl_g = gVtl + (size_t)b * NE * NS;

    if (tid < 64) rs[tid] = kScale * (float)mask[b * NS + q0 + tid];

    // pass-1 preload: Q hi/lo + K0(hh) as one group
    load64img(sm + SM_QH, Qh_g, tid);
    load64img(sm + SM_QL, Ql_g, tid);
    load64img(sm + SM_KH, Kh_g, tid);
    cp_commit();

    // ================= pass 1: raw row max from Qh x Kh =================
    float rmax_l = -1e30f, rmax_h = -1e30f;
    for (int kt = 0; kt < 32; kt++) {
        u32 kbuf = (kt & 1) ? (sm + SM_KL) : (sm + SM_KH);
        if (kt + 1 < 32) {
            u32 nbuf = (kt & 1) ? (sm + SM_KH) : (sm + SM_KL);
            load64img(nbuf, Kh_g + (size_t)(kt + 1) * 64 * NE, tid);
            cp_commit();
            cp_wait1();
        } else {
            cp_wait0();
        }
        __syncthreads();
        float S0[4] = {0.f, 0.f, 0.f, 0.f}, S1[4] = {0.f, 0.f, 0.f, 0.f};
#pragma unroll
        for (int st = 0; st < 16; st++) {
            u32 a[4], bq[4];
            lda(a, sm + SM_QH, r0, st * 32, lane, true);
            ldb(bq, kbuf, n0, st * 32, lane, true);
            mma_bf16(S0, a, bq[0], bq[1]);
            mma_bf16(S1, a, bq[2], bq[3]);
        }
        rmax_l = fmaxf(rmax_l, fmaxf(fmaxf(S0[0], S0[1]), fmaxf(S1[0], S1[1])));
        rmax_h = fmaxf(rmax_h, fmaxf(fmaxf(S0[2], S0[3]), fmaxf(S1[2], S1[3])));
        __syncthreads();
    }
    rmax_l = fmaxf(rmax_l, __shfl_xor_sync(~0u, rmax_l, 1));
    rmax_l = fmaxf(rmax_l, __shfl_xor_sync(~0u, rmax_l, 2));
    rmax_h = fmaxf(rmax_h, __shfl_xor_sync(~0u, rmax_h, 1));
    rmax_h = fmaxf(rmax_h, __shfl_xor_sync(~0u, rmax_h, 2));
    if ((lane & 3) == 0) { red[wn * 64 + rl] = rmax_l; red[wn * 64 + rh] = rmax_h; }
    __syncthreads();
    const float rsc_l = rs[rl], rsc_h = rs[rh];
    const float m_l = fmaxf(fmaxf(red[rl], red[64 + rl]), fmaxf(red[128 + rl], red[192 + rl])) * rsc_l;
    const float m_h = fmaxf(fmaxf(red[rh], red[64 + rh]), fmaxf(red[128 + rh], red[192 + rh])) * rsc_h;
    __syncthreads();

    // ================= pass 2 =================
    load64img(sm + SM_KH, Kh_g, tid);
    load64img(sm + SM_KL, Kl_g, tid);
    cp_commit();                       // group K(0)
    loadvt(sm + SM_VH, Vth_g, tid);
    loadvt(sm + SM_VL, Vtl_g, tid);
    cp_commit();                       // group V(0)

    float O[8][4];
#pragma unroll
    for (int i = 0; i < 8; i++)
#pragma unroll
        for (int j = 0; j < 4; j++) O[i][j] = 0.f;
    float l_l = 0.f, l_h = 0.f;

    for (int kt = 0; kt < 32; kt++) {
        cp_wait1();        // K(kt) resident; V(kt) may be in flight
        __syncthreads();

        // ---- QK 4-way split ----
        float S0[4] = {0.f, 0.f, 0.f, 0.f}, S1[4] = {0.f, 0.f, 0.f, 0.f};
#pragma unroll
        for (int st = 0; st < 16; st++) {
            u32 ah[4], al[4], bh[4], bl[4];
            lda(ah, sm + SM_QH, r0, st * 32, lane, true);
            lda(al, sm + SM_QL, r0, st * 32, lane, true);
            ldb(bh, sm + SM_KH, n0, st * 32, lane, true);
            ldb(bl, sm + SM_KL, n0, st * 32, lane, true);
            mma_bf16(S0, ah, bh[0], bh[1]); mma_bf16(S1, ah, bh[2], bh[3]);
            mma_bf16(S0, ah, bl[0], bl[1]); mma_bf16(S1, ah, bl[2], bl[3]);
            mma_bf16(S0, al, bh[0], bh[1]); mma_bf16(S1, al, bh[2], bh[3]);
            mma_bf16(S0, al, bl[0], bl[1]); mma_bf16(S1, al, bl[2], bl[3]);
        }
        __syncthreads();   // all warps done reading K

        if (kt + 1 < 32) { // prefetch K(kt+1), overlaps softmax + PV
            load64img(sm + SM_KH, Kh_g + (size_t)(kt + 1) * 64 * NE, tid);
            load64img(sm + SM_KL, Kl_g + (size_t)(kt + 1) * 64 * NE, tid);
            cp_commit();
        }

        // ---- softmax + P pack (this warp's 16q x 16k patch) ----
        {
            float p00 = __expf(S0[0] * rsc_l - m_l);
            float p01 = __expf(S0[1] * rsc_l - m_l);
            float p10 = __expf(S1[0] * rsc_l - m_l);
            float p11 = __expf(S1[1] * rsc_l - m_l);
            float q00 = __expf(S0[2] * rsc_h - m_h);
            float q01 = __expf(S0[3] * rsc_h - m_h);
            float q10 = __expf(S1[2] * rsc_h - m_h);
            float q11 = __expf(S1[3] * rsc_h - m_h);
            l_l += p00 + p01 + p10 + p11;
            l_h += q00 + q01 + q10 + q11;
            int cb = (n0 + 2 * (lane & 3)) * 2;
            u32 h0, l0, h1, l1, h2, l2, h3, l3;
            packsplit(p00, p01, h0, l0);
            packsplit(p10, p11, h1, l1);
            packsplit(q00, q01, h2, l2);
            packsplit(q10, q11, h3, l3);
            *(u32*)(smc + SM_PH + off128(rl, cb))      = h0;
            *(u32*)(smc + SM_PH + off128(rl, cb + 16)) = h1;
            *(u32*)(smc + SM_PH + off128(rh, cb))      = h2;
            *(u32*)(smc + SM_PH + off128(rh, cb + 16)) = h3;
            *(u32*)(smc + SM_PL + off128(rl, cb))      = l0;
            *(u32*)(smc + SM_PL + off128(rl, cb + 16)) = l1;
            *(u32*)(smc + SM_PL + off128(rh, cb))      = l2;
            *(u32*)(smc + SM_PL + off128(rh, cb + 16)) = l3;
        }

        if (kt == 31) cp_wait0(); else cp_wait1();   // V(kt) resident
        __syncthreads();   // P visible to all; V visible

        // ---- PV 3-way split: O[16q x 64e] += P * V ----
#pragma unroll
        for (int kk = 0; kk < 4; kk++) {
            u32 ph[4], pl[4];
            lda(ph, sm + SM_PH, r0, kk * 32, lane, false);
            lda(pl, sm + SM_PL, r0, kk * 32, lane, false);
#pragma unroll
            for (int np = 0; np < 4; np++) {
                u32 vh[4], vl[4];
                ldb(vh, sm + SM_VH, e0 + np * 16, kk * 32, lane, false);
                ldb(vl, sm + SM_VL, e0 + np * 16, kk * 32, lane, false);
                mma_bf16(O[np * 2],     ph, vh[0], vh[1]);
                mma_bf16(O[np * 2 + 1], ph, vh[2], vh[3]);
                mma_bf16(O[np * 2],     ph, vl[0], vl[1]);
                mma_bf16(O[np * 2 + 1], ph, vl[2], vl[3]);
                mma_bf16(O[np * 2],     pl, vh[0], vh[1]);
                mma_bf16(O[np * 2 + 1], pl, vh[2], vh[3]);
            }
        }
        __syncthreads();   // all warps done reading V

        if (kt + 1 < 32) { // prefetch V(kt+1), overlaps next QK
            loadvt(sm + SM_VH, Vth_g + (size_t)(kt + 1) * 64, tid);
            loadvt(sm + SM_VL, Vtl_g + (size_t)(kt + 1) * 64, tid);
            cp_commit();
        }
    }

    // ================= epilogue =================
    l_l += __shfl_xor_sync(~0u, l_l, 1);
    l_l += __shfl_xor_sync(~0u, l_l, 2);
    l_h += __shfl_xor_sync(~0u, l_h, 1);
    l_h += __shfl_xor_sync(~0u, l_h, 2);
    if ((lane & 3) == 0) { red[wn * 64 + rl] = l_l; red[wn * 64 + rh] = l_h; }
    __syncthreads();
    const float inv_l = 1.0f / (red[rl] + red[64 + rl] + red[128 + rl] + red[192 + rl]);
    const float inv_h = 1.0f / (red[rh] + red[64 + rh] + red[128 + rh] + red[192 + rh]);

    float* orow_l = out + (size_t)(b * NS + q0 + rl) * NE;
    float* orow_h = out + (size_t)(b * NS + q0 + rh) * NE;
#pragma unroll
    for (int nt = 0; nt < 8; nt++) {
        int col = e0 + nt * 8 + 2 * (lane & 3);
        *(float2*)&orow_l[col] = make_float2(O[nt][0] * inv_l, O[nt][1] * inv_l);
        *(float2*)&orow_h[col] = make_float2(O[nt][2] * inv_h, O[nt][3] * inv_h);
    }
}

// ---------------------------------------------------------------------------
extern "C" void kernel_launch(void* const* d_in, const int* in_sizes, int n_in,
                              void* d_out, int out_size) {
    (void)in_sizes; (void)n_in; (void)out_size;
    const float* x    = (const float*)d_in[0];
    const float* w    = (const float*)d_in[1];
    const int*   mask = (const int*)d_in[2];
    float* out = (float*)d_out;

    dim3 g1((NB * NS) / 64, NE / 64);
    qkv_prep<<<g1, 256>>>(x, w);

    cudaFuncSetAttribute(attn_mma, cudaFuncAttributeMaxDynamicSharedMemorySize, SM_TOT);
    dim3 g2(NS / 64, NB);
    attn_mma<<<g2, 512, SM_TOT>>>(mask, out);
}

// round 11
// speedup vs baseline: 1.9962x; 1.1730x over previous
#include <cuda_runtime.h>
#include <cuda_bf16.h>
#include <math.h>
#include <stdint.h>

#define NB 8
#define NS 2048
#define ND 256
#define NE 256
static constexpr float kScale = 0.125f;  // 1/sqrt(64), per reference source

typedef unsigned long long u64;
typedef uint32_t u32;
typedef unsigned short u16;

// ---------------- packed f32x2 (prep GEMM) ----------------
__device__ __forceinline__ u64 pack2(float x, float y) {
    u64 r;
    asm("mov.b64 %0, {%1, %2};" : "=l"(r) : "r"(__float_as_uint(x)), "r"(__float_as_uint(y)));
    return r;
}
__device__ __forceinline__ void unpack2(u64 v, float& x, float& y) {
    unsigned lo, hi;
    asm("mov.b64 {%0, %1}, %2;" : "=r"(lo), "=r"(hi) : "l"(v));
    x = __uint_as_float(lo);
    y = __uint_as_float(hi);
}
__device__ __forceinline__ void ffma2(u64& d, u64 a, u64 b) {
    asm("fma.rn.f32x2 %0, %1, %2, %0;" : "+l"(d) : "l"(a), "l"(b));
}

// ---------------- cp.async ----------------
__device__ __forceinline__ void cp16(u32 smem_dst, const void* gmem_src) {
    asm volatile("cp.async.cg.shared.global [%0], [%1], 16;" :: "r"(smem_dst), "l"(gmem_src));
}
__device__ __forceinline__ void cp_commit() {
    asm volatile("cp.async.commit_group;" ::: "memory");
}
__device__ __forceinline__ void cp_wait0() { asm volatile("cp.async.wait_group 0;" ::: "memory"); }
__device__ __forceinline__ void cp_wait1() { asm volatile("cp.async.wait_group 1;" ::: "memory"); }

// ---------------- mma.sync / ldmatrix (family-wide, works on sm_103) ----------
__device__ __forceinline__ void ldsm4(u32* d, u32 addr) {
    asm volatile("ldmatrix.sync.aligned.m8n8.x4.shared.b16 {%0,%1,%2,%3}, [%4];"
        : "=r"(d[0]), "=r"(d[1]), "=r"(d[2]), "=r"(d[3]) : "r"(addr));
}
__device__ __forceinline__ void mma_bf16(float* c, const u32* a, u32 b0, u32 b1) {
    asm volatile("mma.sync.aligned.m16n8k16.row.col.f32.bf16.bf16.f32 "
        "{%0,%1,%2,%3}, {%4,%5,%6,%7}, {%8,%9}, {%0,%1,%2,%3};"
        : "+f"(c[0]), "+f"(c[1]), "+f"(c[2]), "+f"(c[3])
        : "r"(a[0]), "r"(a[1]), "r"(a[2]), "r"(a[3]), "r"(b0), "r"(b1));
}

// ---------------- global bf16 scratch ----------------
__device__ __align__(16) __nv_bfloat16 gQh[NB * NS * NE];
__device__ __align__(16) __nv_bfloat16 gQl[NB * NS * NE];
__device__ __align__(16) __nv_bfloat16 gKh[NB * NS * NE];
__device__ __align__(16) __nv_bfloat16 gKl[NB * NS * NE];
__device__ __align__(16) __nv_bfloat16 gVth[NB * NE * NS];
__device__ __align__(16) __nv_bfloat16 gVtl[NB * NE * NS];

// ---------------------------------------------------------------------------
// Prep: fp32 QKV GEMM (FFMA2) + bf16 hi/lo split stores.
// ---------------------------------------------------------------------------
__global__ __launch_bounds__(256) void qkv_prep(const float* __restrict__ x,
                                                const float* __restrict__ w) {
    __shared__ __align__(16) float As[64][20];
    __shared__ __align__(16) float Bs[3][16][68];

    const int row0 = blockIdx.x * 64;
    const int col0 = blockIdx.y * 64;
    const int tid = threadIdx.x;
    const int tx = tid & 15;
    const int ty = tid >> 4;

    ulonglong2 acc[3][4];
#pragma unroll
    for (int p = 0; p < 3; p++)
#pragma unroll
        for (int i = 0; i < 4; i++) { acc[p][i].x = 0ull; acc[p][i].y = 0ull; }

    for (int k0 = 0; k0 < ND; k0 += 16) {
        {
            int r = tid >> 2, c = (tid & 3) << 2;
            cp16((u32)__cvta_generic_to_shared(&As[r][c]), &x[(size_t)(row0 + r) * ND + k0 + c]);
        }
        {
            int r = tid >> 4, c = (tid & 15) << 2;
#pragma unroll
            for (int p = 0; p < 3; p++)
                cp16((u32)__cvta_generic_to_shared(&Bs[p][r][c]),
                     &w[(size_t)p * ND * NE + (size_t)(k0 + r) * NE + col0 + c]);
        }
        cp_commit();
        cp_wait0();
        __syncthreads();
#pragma unroll
        for (int kk = 0; kk < 16; kk++) {
            ulonglong2 bv[3];
#pragma unroll
            for (int p = 0; p < 3; p++) bv[p] = *(const ulonglong2*)&Bs[p][kk][tx << 2];
#pragma unroll
            for (int i = 0; i < 4; i++) {
                float a = As[(ty << 2) + i][kk];
                u64 ap = pack2(a, a);
#pragma unroll
                for (int p = 0; p < 3; p++) {
                    ffma2(acc[p][i].x, ap, bv[p].x);
                    ffma2(acc[p][i].y, ap, bv[p].y);
                }
            }
        }
        __syncthreads();
    }

    auto split4 = [](const ulonglong2& a, float* f) {
        unpack2(a.x, f[0], f[1]);
        unpack2(a.y, f[2], f[3]);
    };
    auto pack4 = [](const float* f, uint2& hi, uint2& lo) {
        u16 h[4], l[4];
#pragma unroll
        for (int j = 0; j < 4; j++) {
            __nv_bfloat16 hb = __float2bfloat16_rn(f[j]);
            __nv_bfloat16 lb = __float2bfloat16_rn(f[j] - __bfloat162float(hb));
            h[j] = __bfloat16_as_ushort(hb);
            l[j] = __bfloat16_as_ushort(lb);
        }
        hi.x = (u32)h[0] | ((u32)h[1] << 16); hi.y = (u32)h[2] | ((u32)h[3] << 16);
        lo.x = (u32)l[0] | ((u32)l[1] << 16); lo.y = (u32)l[2] | ((u32)l[3] << 16);
    };

    float vf[4][4];
#pragma unroll
    for (int i = 0; i < 4; i++) {
        size_t off = (size_t)(row0 + (ty << 2) + i) * NE + col0 + (tx << 2);
        float f[4];
        uint2 hi, lo;
        split4(acc[0][i], f); pack4(f, hi, lo);
        *(uint2*)&gQh[off] = hi; *(uint2*)&gQl[off] = lo;
        split4(acc[1][i], f); pack4(f, hi, lo);
        *(uint2*)&gKh[off] = hi; *(uint2*)&gKl[off] = lo;
        split4(acc[2][i], vf[i]);
    }
    const int b = row0 >> 11;
    const int key0 = (row0 & (NS - 1)) + (ty << 2);
#pragma unroll
    for (int j = 0; j < 4; j++) {
        int e = col0 + (tx << 2) + j;
        float f[4] = {vf[0][j], vf[1][j], vf[2][j], vf[3][j]};
        uint2 hi, lo;
        pack4(f, hi, lo);
        size_t off = (size_t)b * NE * NS + (size_t)e * NS + key0;
        *(uint2*)&gVth[off] = hi; *(uint2*)&gVtl[off] = lo;
    }
}

// ---------------------------------------------------------------------------
// Attention: 64 q per block, 512 threads (16 warps: 4 q-groups x 4 key/e-grps).
// SINGLE PASS with online softmax (cross-warp row max via smem exchange
// piggybacked on the post-QK barrier). mma.sync m16n8k16 bf16,
// 4-way split QK, 3-way split PV. 128B-atom XOR-swizzled smem images.
// ---------------------------------------------------------------------------
#define SM_RS   0                      // 64 floats: row scale
#define SM_RED  256                    // 4*64 floats: max / l reduction
#define SM_QH   2048                   // 64x256 bf16 images, 32KB each
#define SM_QL   (SM_QH + 32768)
#define SM_KH   (SM_QL + 32768)
#define SM_KL   (SM_KH + 32768)
#define SM_VH   (SM_KL + 32768)        // Vt: 256 e-rows x 64 keys
#define SM_VL   (SM_VH + 32768)
#define SM_PH   (SM_VL + 32768)        // P: 64 q-rows x 64 keys, 8KB each
#define SM_PL   (SM_PH + 8192)
#define SM_TOT  (SM_PL + 8192)         // 215040 B

__device__ __forceinline__ u32 swz(u32 o) { return o ^ ((o >> 3) & 0x70); }
__device__ __forceinline__ u32 off64(int r, int cb) {
    return swz((u32)(((r >> 3) + (cb >> 7) * 8) * 1024 + (r & 7) * 128 + (cb & 127)));
}
__device__ __forceinline__ u32 off128(int r, int cb) {
    return swz((u32)(r * 128 + cb));
}

__device__ __forceinline__ void lda(u32* d, u32 base, int r0, int cb, int lane, bool wide) {
    int g = lane >> 3;
    int r = r0 + (lane & 7) + (g & 1) * 8;
    int c = cb + (g >> 1) * 16;
    ldsm4(d, base + (wide ? off64(r, c) : off128(r, c)));
}
__device__ __forceinline__ void ldb(u32* d, u32 base, int n0, int cb, int lane, bool wide) {
    int g = lane >> 3;
    int r = n0 + (lane & 7) + (g >> 1) * 8;
    int c = cb + (g & 1) * 16;
    ldsm4(d, base + (wide ? off64(r, c) : off128(r, c)));
}

__device__ __forceinline__ void load64img(u32 base, const __nv_bfloat16* src, int tid) {
    for (int c = tid; c < 2048; c += 512) {
        int r = c >> 5, eb = (c & 31) << 4;
        cp16(base + off64(r, eb), (const char*)src + (size_t)r * 512 + eb);
    }
}
__device__ __forceinline__ void loadvt(u32 base, const __nv_bfloat16* src, int tid) {
    for (int c = tid; c < 2048; c += 512) {
        int e = c >> 3, kb = (c & 7) << 4;
        cp16(base + off128(e, kb), (const char*)src + (size_t)e * (NS * 2) + kb);
    }
}

__device__ __forceinline__ void packsplit(float x, float y, u32& hi, u32& lo) {
    __nv_bfloat16 xh = __float2bfloat16_rn(x), yh = __float2bfloat16_rn(y);
    __nv_bfloat16 xl = __float2bfloat16_rn(x - __bfloat162float(xh));
    __nv_bfloat16 yl = __float2bfloat16_rn(y - __bfloat162float(yh));
    hi = (u32)__bfloat16_as_ushort(xh) | ((u32)__bfloat16_as_ushort(yh) << 16);
    lo = (u32)__bfloat16_as_ushort(xl) | ((u32)__bfloat16_as_ushort(yl) << 16);
}

__global__ __launch_bounds__(512, 1) void attn_mma(const int* __restrict__ mask,
                                                   float* __restrict__ out) {
    extern __shared__ __align__(1024) char smc[];
    const u32 sm = (u32)__cvta_generic_to_shared(smc);
    float* rs = (float*)(smc + SM_RS);
    float* red = (float*)(smc + SM_RED);

    const int b = blockIdx.y, q0 = blockIdx.x * 64;
    const int tid = threadIdx.x, lane = tid & 31, wid = tid >> 5;
    const int wq = wid & 3, wn = wid >> 2;
    const int r0 = wq * 16;
    const int rl = r0 + (lane >> 2), rh = rl + 8;
    const int n0 = wn * 16;          // QK key chunk
    const int e0 = wn * 64;          // PV e chunk

    const __nv_bfloat16* Qh_g = gQh + (size_t)(b * NS + q0) * NE;
    const __nv_bfloat16* Ql_g = gQl + (size_t)(b * NS + q0) * NE;
    const __nv_bfloat16* Kh_g = gKh + (size_t)b * NS * NE;
    const __nv_bfloat16* Kl_g = gKl + (size_t)b * NS * NE;
    const __nv_bfloat16* Vth_g = gVth + (size_t)b * NE * NS;
    const __nv_bfloat16* Vtl_g = gVtl + (size_t)b * NE * NS;

    if (tid < 64) rs[tid] = kScale * (float)mask[b * NS + q0 + tid];

    // preload: Q hi/lo (resident all kernel), then K(0) group, then V(0) group
    load64img(sm + SM_QH, Qh_g, tid);
    load64img(sm + SM_QL, Ql_g, tid);
    load64img(sm + SM_KH, Kh_g, tid);
    load64img(sm + SM_KL, Kl_g, tid);
    cp_commit();                       // group: Q + K(0)
    loadvt(sm + SM_VH, Vth_g, tid);
    loadvt(sm + SM_VL, Vtl_g, tid);
    cp_commit();                       // group: V(0)
    __syncthreads();                   // rs visible

    const float rsc_l = rs[rl], rsc_h = rs[rh];

    float O[8][4];
#pragma unroll
    for (int i = 0; i < 8; i++)
#pragma unroll
        for (int j = 0; j < 4; j++) O[i][j] = 0.f;
    float l_l = 0.f, l_h = 0.f;
    float m_l = -1e30f, m_h = -1e30f;

    for (int kt = 0; kt < 32; kt++) {
        cp_wait1();        // K(kt) resident; V(kt) may be in flight
        __syncthreads();

        // ---- QK 4-way split ----
        float S0[4] = {0.f, 0.f, 0.f, 0.f}, S1[4] = {0.f, 0.f, 0.f, 0.f};
#pragma unroll
        for (int st = 0; st < 16; st++) {
            u32 ah[4], al[4], bh[4], bl[4];
            lda(ah, sm + SM_QH, r0, st * 32, lane, true);
            lda(al, sm + SM_QL, r0, st * 32, lane, true);
            ldb(bh, sm + SM_KH, n0, st * 32, lane, true);
            ldb(bl, sm + SM_KL, n0, st * 32, lane, true);
            mma_bf16(S0, ah, bh[0], bh[1]); mma_bf16(S1, ah, bh[2], bh[3]);
            mma_bf16(S0, ah, bl[0], bl[1]); mma_bf16(S1, ah, bl[2], bl[3]);
            mma_bf16(S0, al, bh[0], bh[1]); mma_bf16(S1, al, bh[2], bh[3]);
            mma_bf16(S0, al, bl[0], bl[1]); mma_bf16(S1, al, bl[2], bl[3]);
        }

        // ---- warp-local row max (raw scores), exchange via red ----
        float wm_l = fmaxf(fmaxf(S0[0], S0[1]), fmaxf(S1[0], S1[1]));
        float wm_h = fmaxf(fmaxf(S0[2], S0[3]), fmaxf(S1[2], S1[3]));
        wm_l = fmaxf(wm_l, __shfl_xor_sync(~0u, wm_l, 1));
        wm_l = fmaxf(wm_l, __shfl_xor_sync(~0u, wm_l, 2));
        wm_h = fmaxf(wm_h, __shfl_xor_sync(~0u, wm_h, 1));
        wm_h = fmaxf(wm_h, __shfl_xor_sync(~0u, wm_h, 2));
        if ((lane & 3) == 0) { red[wn * 64 + rl] = wm_l; red[wn * 64 + rh] = wm_h; }
        __syncthreads();   // K reads done (prefetch may overwrite) + red visible

        if (kt + 1 < 32) { // prefetch K(kt+1): overlaps softmax + PV
            load64img(sm + SM_KH, Kh_g + (size_t)(kt + 1) * 64 * NE, tid);
            load64img(sm + SM_KL, Kl_g + (size_t)(kt + 1) * 64 * NE, tid);
            cp_commit();
        }

        // ---- online max update + O/l rescale ----
        float nm_l = fmaxf(fmaxf(red[rl], red[64 + rl]),
                           fmaxf(red[128 + rl], red[192 + rl])) * rsc_l;
        float nm_h = fmaxf(fmaxf(red[rh], red[64 + rh]),
                           fmaxf(red[128 + rh], red[192 + rh])) * rsc_h;
        nm_l = fmaxf(m_l, nm_l);
        nm_h = fmaxf(m_h, nm_h);
        const float al_l = __expf(m_l - nm_l), al_h = __expf(m_h - nm_h);
        m_l = nm_l; m_h = nm_h;
#pragma unroll
        for (int nt = 0; nt < 8; nt++) {
            O[nt][0] *= al_l; O[nt][1] *= al_l;
            O[nt][2] *= al_h; O[nt][3] *= al_h;
        }

        // ---- softmax + P pack (this warp's 16q x 16k patch) ----
        {
            float p00 = __expf(S0[0] * rsc_l - m_l);
            float p01 = __expf(S0[1] * rsc_l - m_l);
            float p10 = __expf(S1[0] * rsc_l - m_l);
            float p11 = __expf(S1[1] * rsc_l - m_l);
            float q00 = __expf(S0[2] * rsc_h - m_h);
            float q01 = __expf(S0[3] * rsc_h - m_h);
            float q10 = __expf(S1[2] * rsc_h - m_h);
            float q11 = __expf(S1[3] * rsc_h - m_h);
            l_l = l_l * al_l + (p00 + p01 + p10 + p11);
            l_h = l_h * al_h + (q00 + q01 + q10 + q11);
            int cb = (n0 + 2 * (lane & 3)) * 2;
            u32 h0, l0, h1, l1, h2, l2, h3, l3;
            packsplit(p00, p01, h0, l0);
            packsplit(p10, p11, h1, l1);
            packsplit(q00, q01, h2, l2);
            packsplit(q10, q11, h3, l3);
            *(u32*)(smc + SM_PH + off128(rl, cb))      = h0;
            *(u32*)(smc + SM_PH + off128(rl, cb + 16)) = h1;
            *(u32*)(smc + SM_PH + off128(rh, cb))      = h2;
            *(u32*)(smc + SM_PH + off128(rh, cb + 16)) = h3;
            *(u32*)(smc + SM_PL + off128(rl, cb))      = l0;
            *(u32*)(smc + SM_PL + off128(rl, cb + 16)) = l1;
            *(u32*)(smc + SM_PL + off128(rh, cb))      = l2;
            *(u32*)(smc + SM_PL + off128(rh, cb + 16)) = l3;
        }

        if (kt == 31) cp_wait0(); else cp_wait1();   // V(kt) resident
        __syncthreads();   // P visible to all; V visible

        // ---- PV 3-way split: O[16q x 64e] += P * V ----
#pragma unroll
        for (int kk = 0; kk < 4; kk++) {
            u32 ph[4], pl[4];
            lda(ph, sm + SM_PH, r0, kk * 32, lane, false);
            lda(pl, sm + SM_PL, r0, kk * 32, lane, false);
#pragma unroll
            for (int np = 0; np < 4; np++) {
                u32 vh[4], vl[4];
                ldb(vh, sm + SM_VH, e0 + np * 16, kk * 32, lane, false);
                ldb(vl, sm + SM_VL, e0 + np * 16, kk * 32, lane, false);
                mma_bf16(O[np * 2],     ph, vh[0], vh[1]);
                mma_bf16(O[np * 2 + 1], ph, vh[2], vh[3]);
                mma_bf16(O[np * 2],     ph, vl[0], vl[1]);
                mma_bf16(O[np * 2 + 1], ph, vl[2], vl[3]);
                mma_bf16(O[np * 2],     pl, vh[0], vh[1]);
                mma_bf16(O[np * 2 + 1], pl, vh[2], vh[3]);
            }
        }
        __syncthreads();   // all warps done reading V (and P)

        if (kt + 1 < 32) { // prefetch V(kt+1): overlaps next QK
            loadvt(sm + SM_VH, Vth_g + (size_t)(kt + 1) * 64, tid);
            loadvt(sm + SM_VL, Vtl_g + (size_t)(kt + 1) * 64, tid);
            cp_commit();
        }
    }

    // ================= epilogue =================
    l_l += __shfl_xor_sync(~0u, l_l, 1);
    l_l += __shfl_xor_sync(~0u, l_l, 2);
    l_h += __shfl_xor_sync(~0u, l_h, 1);
    l_h += __shfl_xor_sync(~0u, l_h, 2);
    if ((lane & 3) == 0) { red[wn * 64 + rl] = l_l; red[wn * 64 + rh] = l_h; }
    __syncthreads();
    const float inv_l = 1.0f / (red[rl] + red[64 + rl] + red[128 + rl] + red[192 + rl]);
    const float inv_h = 1.0f / (red[rh] + red[64 + rh] + red[128 + rh] + red[192 + rh]);

    float* orow_l = out + (size_t)(b * NS + q0 + rl) * NE;
    float* orow_h = out + (size_t)(b * NS + q0 + rh) * NE;
#pragma unroll
    for (int nt = 0; nt < 8; nt++) {
        int col = e0 + nt * 8 + 2 * (lane & 3);
        *(float2*)&orow_l[col] = make_float2(O[nt][0] * inv_l, O[nt][1] * inv_l);
        *(float2*)&orow_h[col] = make_float2(O[nt][2] * inv_h, O[nt][3] * inv_h);
    }
}

// ---------------------------------------------------------------------------
extern "C" void kernel_launch(void* const* d_in, const int* in_sizes, int n_in,
                              void* d_out, int out_size) {
    (void)in_sizes; (void)n_in; (void)out_size;
    const float* x    = (const float*)d_in[0];
    const float* w    = (const float*)d_in[1];
    const int*   mask = (const int*)d_in[2];
    float* out = (float*)d_out;

    dim3 g1((NB * NS) / 64, NE / 64);
    qkv_prep<<<g1, 256>>>(x, w);

    cudaFuncSetAttribute(attn_mma, cudaFuncAttributeMaxDynamicSharedMemorySize, SM_TOT);
    dim3 g2(NS / 64, NB);
    attn_mma<<<g2, 512, SM_TOT>>>(mask, out);
}